// round 13
// baseline (speedup 1.0000x reference)
#include <cuda_runtime.h>
#include <math.h>
#include <stdint.h>

// ---------------- problem constants ----------------
#define MTOT 36992            // 32 * 34 * 34 flattened padded rows
#define KTOT 2304             // 9 taps * 256 channels
#define CHUNKS 18             // 9 taps * 2 half-channel groups (128B of K each)
#define STAGES 3
#define AROWS 198             // rows m0-35 .. m0+162

// ---------------- device scratch (no allocs allowed) ----------------
__device__ __align__(256) int8_t g_xq[(size_t)32 * 34 * 34 * 256]; // [b][hp][wp][c], halo zero
__device__ __align__(256) int8_t g_wq[(size_t)256 * KTOT];         // [o][tap*256 + c] ternary
__device__ float g_scale[256];
__device__ float g_bias[256];

// ---------------------------------------------------------------------------
// Pre-pass A: quantize x to int8 (scale 2^-7), NCHW -> padded NHWC
// ---------------------------------------------------------------------------
__global__ void quantX_kernel(const float* __restrict__ x) {
    __shared__ int8_t s[256][33];
    int b = blockIdx.x, h = blockIdx.y;
    int w  = threadIdx.x & 31;
    int cg = threadIdx.x >> 5;
#pragma unroll
    for (int c0 = 0; c0 < 256; c0 += 8) {
        int c = c0 + cg;
        float v = x[(((size_t)(b * 256 + c) * 32 + h) * 32) + w];
        float r = rintf(v * 128.0f);
        r = fminf(fmaxf(r, -128.0f), 127.0f);
        s[c][w] = (int8_t)(int)r;
    }
    __syncthreads();
    size_t base = (((size_t)(b * 34 + h + 1)) * 34 + 1) * 256;
#pragma unroll
    for (int it = 0; it < 8; ++it) {
        int idx = it * 256 + threadIdx.x;
        int w2 = idx >> 6, cw = idx & 63;
        char4 v;
        v.x = s[cw * 4 + 0][w2];
        v.y = s[cw * 4 + 1][w2];
        v.z = s[cw * 4 + 2][w2];
        v.w = s[cw * 4 + 3][w2];
        *reinterpret_cast<char4*>(&g_xq[base + (size_t)w2 * 256 + cw * 4]) = v;
    }
}

// ---------------------------------------------------------------------------
// Pre-pass B: ternary weights, OIHW -> [o][tap*256 + c]
// ---------------------------------------------------------------------------
__global__ void quantW_kernel(const float* __restrict__ wt) {
    int idx = blockIdx.x * 256 + threadIdx.x;   // 589824 total
    int o = idx / KTOT;
    int r = idx - o * KTOT;
    int t = r >> 8;
    int c = r & 255;
    float v = wt[((size_t)(o * 256 + c)) * 9 + t];
    float q = rintf(v);
    q = fminf(fmaxf(q, -1.0f), 1.0f);
    g_wq[(size_t)o * KTOT + r] = (int8_t)(int)q;
}

// ---------------------------------------------------------------------------
// Pre-pass C: BN fold
// ---------------------------------------------------------------------------
__global__ void bn_kernel(const float* __restrict__ g, const float* __restrict__ be,
                          const float* __restrict__ m, const float* __restrict__ v) {
    int o = threadIdx.x;
    double invd = (double)g[o] / sqrt((double)v[o] + 1e-4);
    float invf = (float)invd;
    g_scale[o] = invf;
    g_bias[o]  = __fadd_rn(be[o], -__fmul_rn(m[o], invf));
}

// ---------------- helpers ----------------
__device__ __forceinline__ uint32_t smem_u32(const void* p) {
    uint32_t a;
    asm("{ .reg .u64 t; cvta.to.shared.u64 t, %1; cvt.u32.u64 %0, t; }" : "=r"(a) : "l"(p));
    return a;
}
__device__ __forceinline__ void cp_async_16(uint32_t dst, const void* src, unsigned srcsz) {
    asm volatile("cp.async.cg.shared.global [%0], [%1], 16, %2;"
                 :: "r"(dst), "l"(src), "r"(srcsz));
}
__device__ __forceinline__ void ldsm_x4(uint32_t* r, uint32_t addr) {
    asm volatile("ldmatrix.sync.aligned.m8n8.x4.shared.b16 {%0,%1,%2,%3}, [%4];"
                 : "=r"(r[0]), "=r"(r[1]), "=r"(r[2]), "=r"(r[3]) : "r"(addr));
}
__device__ __forceinline__ void imma(int* c, const uint32_t* a, uint32_t b0, uint32_t b1) {
    asm volatile(
        "mma.sync.aligned.m16n8k32.row.col.s32.s8.s8.s32 "
        "{%0,%1,%2,%3}, {%4,%5,%6,%7}, {%8,%9}, {%0,%1,%2,%3};"
        : "+r"(c[0]), "+r"(c[1]), "+r"(c[2]), "+r"(c[3])
        : "r"(a[0]), "r"(a[1]), "r"(a[2]), "r"(a[3]), "r"(b0), "r"(b1));
}

// smem: A persistent [198 rows x 256B] = 50688, then B ring 3 x 16384 = 49152
#define A_BYTES   50688
#define BSTAGE_SZ 16384
#define SMEM_BYTES (A_BYTES + STAGES * BSTAGE_SZ)   // 99840 -> 2 CTAs/SM
#define EPS 129

__global__ void __launch_bounds__(256, 2) conv_hybrid_kernel(float* __restrict__ out) {
    extern __shared__ __align__(256) char smem[];
    const uint32_t sb = smem_u32(smem);
    const int tid  = threadIdx.x;
    const int wid  = tid >> 5;
    const int lane = tid & 31;
    const int m0 = blockIdx.x * 128;
    const int n0 = blockIdx.y * 128;

    // Every warp carries BOTH an IMMA sub-tile and a dp4a strip.
    int acc[4][2][4];     // IMMA: warp tile 64M x 16N over local N[0:64]
    int accd[4][8];       // dp4a: 4m x 8o over local N[64:128]
#pragma unroll
    for (int mt = 0; mt < 4; ++mt)
#pragma unroll
        for (int nt = 0; nt < 2; ++nt)
#pragma unroll
            for (int r = 0; r < 4; ++r) acc[mt][nt][r] = 0;
#pragma unroll
    for (int i = 0; i < 4; ++i)
#pragma unroll
        for (int o = 0; o < 8; ++o) accd[i][o] = 0;

    // ---- B-stage loader: all 256 threads, 4 cp.async each ----
    auto load_B = [&](int ks, int stage) {
        const int tap = ks >> 1, hc = ks & 1;
        const uint32_t stB = sb + A_BYTES + stage * BSTAGE_SZ;
#pragma unroll
        for (int it = 0; it < 4; ++it) {
            int idx = it * 256 + tid;          // 0..1023
            int r = idx >> 3, c16 = idx & 7;
            uint32_t soff = (uint32_t)(r * 128 + ((c16 ^ (r & 7)) << 4));
            const int8_t* srcB = g_wq + (size_t)(n0 + r) * KTOT + tap * 256 + hc * 128 + c16 * 16;
            cp_async_16(stB + soff, srcB, 16u);
        }
        asm volatile("cp.async.commit_group;" ::: "memory");
    };

    // ---- prologue: persistent A (198 rows x 256B, zfill halo) + B0, B1 ----
    {
        const long rowbase = (long)m0 - 35;
        for (int idx = tid; idx < AROWS * 16; idx += 256) {
            int r = idx >> 4, c16 = idx & 15;
            uint32_t dst = sb + (uint32_t)(r * 256 + ((c16 ^ (r & 7)) << 4));
            long g = rowbase + r;
            const int8_t* src = g_xq + g * 256 + c16 * 16;
            unsigned sz = (g >= 0 && g < MTOT) ? 16u : 0u;
            cp_async_16(dst, src, sz);
        }
        asm volatile("cp.async.commit_group;" ::: "memory");
        load_B(0, 0);
        load_B(1, 1);
    }

    // IMMA fragment row bases: warps as 2M x 4N (warp N-tile = 16)
    const int wm = wid & 1, wn = wid >> 1;          // wn 0..3
    const int arow_b = wm * 64 + (lane & 15);
    const int ahalf  = lane >> 4;
    const int brow_b = wn * 16 + (lane & 7) + ((lane >> 4) << 3);
    const int bhalf  = (lane >> 3) & 1;
    // phase rotation: the two co-resident warps per SMSP (wid, wid+4) start
    // 2 k32-slices apart -> one feeds tensor while the other feeds fma.
    const int krot = (wid >> 2) << 1;               // 0 or 2

    // ---- mainloop ----
    for (int ks = 0; ks < CHUNKS; ++ks) {
        asm volatile("cp.async.wait_group 1;" ::: "memory");
        __syncthreads();

        int nk = ks + 2;
        if (nk < CHUNKS) load_B(nk, nk % STAGES);
        else asm volatile("cp.async.commit_group;" ::: "memory");

        const int tap = ks >> 1, hc = ks & 1;
        const int aoff = (tap / 3) * 34 + (tap % 3);    // row shift into A buffer (>=0)
        const uint32_t stB = sb + A_BYTES + (ks % STAGES) * BSTAGE_SZ;
        const char* pB = smem + A_BYTES + (ks % STAGES) * BSTAGE_SZ;

#pragma unroll
        for (int kk = 0; kk < 4; ++kk) {
            const int k32 = (kk + krot) & 3;    // integer accs: any order is exact
            // ---- IMMA slice: 1 B-ldsm + 4 A-ldsm + 8 IMMA ----
            uint32_t bb[4];
            {
                uint32_t addr = stB + brow_b * 128 + (((k32 * 2 + bhalf) ^ (brow_b & 7)) << 4);
                ldsm_x4(bb, addr);
            }
#pragma unroll
            for (int mt = 0; mt < 4; ++mt) {
                uint32_t a[4];
                int lr = arow_b + mt * 16 + aoff;
                uint32_t addr = sb + lr * 256 + hc * 128
                              + (((k32 * 2 + ahalf) ^ (lr & 7)) << 4);
                ldsm_x4(a, addr);
                imma(acc[mt][0], a, bb[0], bb[1]);
                imma(acc[mt][1], a, bb[2], bb[3]);
            }
            // ---- dp4a slice: t = 2*k32, 2*k32+1 ----
#pragma unroll
            for (int tt = 0; tt < 2; ++tt) {
                int t = k32 * 2 + tt;
                int4 xv[4];
#pragma unroll
                for (int i = 0; i < 4; ++i) {
                    int lr = lane + 32 * i + aoff;
                    xv[i] = *reinterpret_cast<const int4*>(
                        smem + lr * 256 + hc * 128 + ((t ^ (lr & 7)) << 4));
                }
#pragma unroll
                for (int ob = 0; ob < 2; ++ob) {
                    int4 wv[4];
#pragma unroll
                    for (int oo = 0; oo < 4; ++oo) {
                        int rB = 64 + wid * 8 + ob * 4 + oo;
                        wv[oo] = *reinterpret_cast<const int4*>(pB + rB * 128 + ((t ^ (rB & 7)) << 4));
                    }
#pragma unroll
                    for (int oo = 0; oo < 4; ++oo) {
                        int o = ob * 4 + oo;
#pragma unroll
                        for (int i = 0; i < 4; ++i) {
                            accd[i][o] = __dp4a(xv[i].x, wv[oo].x, accd[i][o]);
                            accd[i][o] = __dp4a(xv[i].y, wv[oo].y, accd[i][o]);
                            accd[i][o] = __dp4a(xv[i].z, wv[oo].z, accd[i][o]);
                            accd[i][o] = __dp4a(xv[i].w, wv[oo].w, accd[i][o]);
                        }
                    }
                }
            }
        }
    }

    // ---- epilogue: all results -> smem -> quantize -> coalesced store ----
    asm volatile("cp.async.wait_group 0;" ::: "memory");
    __syncthreads();
    int* sEp = reinterpret_cast<int*>(smem);      // [128][EPS]
    {
        const int gq = lane >> 2, tg = lane & 3;
#pragma unroll
        for (int mt = 0; mt < 4; ++mt) {
            int m = wm * 64 + mt * 16 + gq;
#pragma unroll
            for (int nt = 0; nt < 2; ++nt) {
                int n = wn * 16 + nt * 8 + tg * 2;
                sEp[m * EPS + n]           = acc[mt][nt][0];
                sEp[m * EPS + n + 1]       = acc[mt][nt][1];
                sEp[(m + 8) * EPS + n]     = acc[mt][nt][2];
                sEp[(m + 8) * EPS + n + 1] = acc[mt][nt][3];
            }
        }
#pragma unroll
        for (int i = 0; i < 4; ++i) {
            int m = lane + 32 * i;
#pragma unroll
            for (int o = 0; o < 8; ++o)
                sEp[m * EPS + 64 + wid * 8 + o] = accd[i][o];
        }
    }
    __syncthreads();

#pragma unroll 4
    for (int i = 0; i < 64; ++i) {
        int idx = i * 256 + tid;
        int m  = idx & 127;
        int oc = idx >> 7;
        int p = m0 + m;
        int b = p / 1156;
        int rem = p - b * 1156;
        int hp = rem / 34;
        int wp = rem - hp * 34;
        if (b < 32 && hp >= 1 && hp <= 32 && wp >= 1 && wp <= 32) {
            int o = n0 + oc;
            float y = __fmul_rn(__fmul_rn((float)sEp[m * EPS + oc], 0.0078125f), g_scale[o]);
            y = __fadd_rn(y, g_bias[o]);
            float r = rintf(__fmul_rn(y, 2.0f));
            r = fminf(fmaxf(r, -2.0f), 1.0f);
            out[(((size_t)b * 256 + o) * 32 + hp - 1) * 32 + wp - 1] = __fmul_rn(r, 0.5f);
        }
    }
}

extern "C" void kernel_launch(void* const* d_in, const int* in_sizes, int n_in,
                              void* d_out, int out_size) {
    const float* x     = (const float*)d_in[0];
    const float* wt    = (const float*)d_in[1];
    const float* gamma = (const float*)d_in[2];
    const float* beta  = (const float*)d_in[3];
    const float* mean  = (const float*)d_in[4];
    const float* var   = (const float*)d_in[5];
    float* out = (float*)d_out;

    void* xq_ptr = nullptr;
    cudaGetSymbolAddress(&xq_ptr, g_xq);
    cudaMemsetAsync(xq_ptr, 0, sizeof(g_xq), 0);

    quantX_kernel<<<dim3(32, 32), 256>>>(x);
    quantW_kernel<<<2304, 256>>>(wt);
    bn_kernel<<<1, 256>>>(gamma, beta, mean, var);

    cudaFuncSetAttribute(conv_hybrid_kernel, cudaFuncAttributeMaxDynamicSharedMemorySize, SMEM_BYTES);
    conv_hybrid_kernel<<<dim3(289, 2), 256, SMEM_BYTES>>>(out);
}

// round 14
// speedup vs baseline: 1.1064x; 1.1064x over previous
#include <cuda_runtime.h>
#include <math.h>
#include <stdint.h>

// ---------------- problem constants ----------------
#define MTOT 36992            // 32 * 34 * 34 flattened padded rows
#define KTOT 2304             // 9 taps * 256 channels
#define CHUNKS 18             // 9 taps * 2 half-channel groups (128B of K each)
#define STAGES 3
#define AROWS 198             // rows m0-35 .. m0+162

// ---------------- device scratch (no allocs allowed) ----------------
__device__ __align__(256) int8_t g_xq[(size_t)32 * 34 * 34 * 256]; // [b][hp][wp][c], halo zero
__device__ __align__(256) int8_t g_wq[(size_t)256 * KTOT];         // [o][tap*256 + c] ternary
__device__ float g_scale[256];
__device__ float g_bias[256];

// ---------------------------------------------------------------------------
// Pre-pass A: quantize x to int8 (scale 2^-7), NCHW -> padded NHWC
// ---------------------------------------------------------------------------
__global__ void quantX_kernel(const float* __restrict__ x) {
    __shared__ int8_t s[256][33];
    int b = blockIdx.x, h = blockIdx.y;
    int w  = threadIdx.x & 31;
    int cg = threadIdx.x >> 5;
#pragma unroll
    for (int c0 = 0; c0 < 256; c0 += 8) {
        int c = c0 + cg;
        float v = x[(((size_t)(b * 256 + c) * 32 + h) * 32) + w];
        float r = rintf(v * 128.0f);
        r = fminf(fmaxf(r, -128.0f), 127.0f);
        s[c][w] = (int8_t)(int)r;
    }
    __syncthreads();
    size_t base = (((size_t)(b * 34 + h + 1)) * 34 + 1) * 256;
#pragma unroll
    for (int it = 0; it < 8; ++it) {
        int idx = it * 256 + threadIdx.x;
        int w2 = idx >> 6, cw = idx & 63;
        char4 v;
        v.x = s[cw * 4 + 0][w2];
        v.y = s[cw * 4 + 1][w2];
        v.z = s[cw * 4 + 2][w2];
        v.w = s[cw * 4 + 3][w2];
        *reinterpret_cast<char4*>(&g_xq[base + (size_t)w2 * 256 + cw * 4]) = v;
    }
}

// ---------------------------------------------------------------------------
// Pre-pass B: ternary weights, OIHW -> [o][tap*256 + c]
// ---------------------------------------------------------------------------
__global__ void quantW_kernel(const float* __restrict__ wt) {
    int idx = blockIdx.x * 256 + threadIdx.x;   // 589824 total
    int o = idx / KTOT;
    int r = idx - o * KTOT;
    int t = r >> 8;
    int c = r & 255;
    float v = wt[((size_t)(o * 256 + c)) * 9 + t];
    float q = rintf(v);
    q = fminf(fmaxf(q, -1.0f), 1.0f);
    g_wq[(size_t)o * KTOT + r] = (int8_t)(int)q;
}

// ---------------------------------------------------------------------------
// Pre-pass C: BN fold
// ---------------------------------------------------------------------------
__global__ void bn_kernel(const float* __restrict__ g, const float* __restrict__ be,
                          const float* __restrict__ m, const float* __restrict__ v) {
    int o = threadIdx.x;
    double invd = (double)g[o] / sqrt((double)v[o] + 1e-4);
    float invf = (float)invd;
    g_scale[o] = invf;
    g_bias[o]  = __fadd_rn(be[o], -__fmul_rn(m[o], invf));
}

// ---------------- helpers ----------------
__device__ __forceinline__ uint32_t smem_u32(const void* p) {
    uint32_t a;
    asm("{ .reg .u64 t; cvta.to.shared.u64 t, %1; cvt.u32.u64 %0, t; }" : "=r"(a) : "l"(p));
    return a;
}
__device__ __forceinline__ void cp_async_16(uint32_t dst, const void* src, unsigned srcsz) {
    asm volatile("cp.async.cg.shared.global [%0], [%1], 16, %2;"
                 :: "r"(dst), "l"(src), "r"(srcsz));
}
__device__ __forceinline__ void ldsm_x4(uint32_t* r, uint32_t addr) {
    asm volatile("ldmatrix.sync.aligned.m8n8.x4.shared.b16 {%0,%1,%2,%3}, [%4];"
                 : "=r"(r[0]), "=r"(r[1]), "=r"(r[2]), "=r"(r[3]) : "r"(addr));
}
__device__ __forceinline__ void imma(int* c, const uint32_t* a, uint32_t b0, uint32_t b1) {
    asm volatile(
        "mma.sync.aligned.m16n8k32.row.col.s32.s8.s8.s32 "
        "{%0,%1,%2,%3}, {%4,%5,%6,%7}, {%8,%9}, {%0,%1,%2,%3};"
        : "+r"(c[0]), "+r"(c[1]), "+r"(c[2]), "+r"(c[3])
        : "r"(a[0]), "r"(a[1]), "r"(a[2]), "r"(a[3]), "r"(b0), "r"(b1));
}

// smem: A persistent [198 rows x 256B] = 50688,
// then per-pair B rings: pair p, stage s at A_BYTES + (p*3+s)*4096
// (each pair slice = 32 rows x 128B: 16 IMMA rows [16p,16p+16) as local 0..15,
//  16 dp4a rows [64+16p, 64+16p+16) as local 16..31)
#define A_BYTES   50688
#define PSTAGE_SZ 4096
#define SMEM_BYTES (A_BYTES + 4 * STAGES * PSTAGE_SZ)   // 99840 -> 2 CTAs/SM
#define EPS 129

__global__ void __launch_bounds__(256, 2) conv_hybrid_kernel(float* __restrict__ out) {
    extern __shared__ __align__(256) char smem[];
    const uint32_t sb = smem_u32(smem);
    const int tid  = threadIdx.x;
    const int wid  = tid >> 5;
    const int lane = tid & 31;
    const int pair = wid >> 1;          // 0..3
    const int ws   = wid & 1;           // warp-in-pair
    const int ptid = tid & 63;          // thread-in-pair
    const int m0 = blockIdx.x * 128;
    const int n0 = blockIdx.y * 128;

    // Every warp carries BOTH an IMMA sub-tile and a dp4a strip.
    int acc[4][2][4];     // IMMA: warp tile 64M x 16N over local N[0:64]
    int accd[4][8];       // dp4a: 4m x 8o over local N[64:128]
#pragma unroll
    for (int mt = 0; mt < 4; ++mt)
#pragma unroll
        for (int nt = 0; nt < 2; ++nt)
#pragma unroll
            for (int r = 0; r < 4; ++r) acc[mt][nt][r] = 0;
#pragma unroll
    for (int i = 0; i < 4; ++i)
#pragma unroll
        for (int o = 0; o < 8; ++o) accd[i][o] = 0;

    // ---- per-pair B-stage loader: 64 threads load the pair's 32 rows ----
    auto load_B = [&](int ks, int stage) {
        const int tap = ks >> 1, hc = ks & 1;
        const uint32_t stB = sb + A_BYTES + (pair * STAGES + stage) * PSTAGE_SZ;
#pragma unroll
        for (int it = 0; it < 4; ++it) {
            int idx = it * 64 + ptid;          // 0..255
            int r = idx >> 3, c16 = idx & 7;   // r 0..31 local
            int grow = (r < 16) ? (16 * pair + r) : (64 + 16 * pair + (r - 16));
            uint32_t soff = (uint32_t)(r * 128 + ((c16 ^ (r & 7)) << 4));
            const int8_t* srcB = g_wq + (size_t)(n0 + grow) * KTOT + tap * 256 + hc * 128 + c16 * 16;
            cp_async_16(stB + soff, srcB, 16u);
        }
        asm volatile("cp.async.commit_group;" ::: "memory");
    };

    // ---- prologue: persistent A (all 256 threads) + per-pair B0, B1 ----
    {
        const long rowbase = (long)m0 - 35;
        for (int idx = tid; idx < AROWS * 16; idx += 256) {
            int r = idx >> 4, c16 = idx & 15;
            uint32_t dst = sb + (uint32_t)(r * 256 + ((c16 ^ (r & 7)) << 4));
            long g = rowbase + r;
            const int8_t* src = g_xq + g * 256 + c16 * 16;
            unsigned sz = (g >= 0 && g < MTOT) ? 16u : 0u;
            cp_async_16(dst, src, sz);
        }
        asm volatile("cp.async.commit_group;" ::: "memory");
        load_B(0, 0);
        load_B(1, 1);
        // A complete for this thread (B0,B1 may remain in flight), publish CTA-wide
        asm volatile("cp.async.wait_group 2;" ::: "memory");
        __syncthreads();
    }

    // IMMA fragment row bases: warps as 2M x 4N (warp N-tile = 16)
    const int wm = wid & 1, wn = wid >> 1;          // wn == pair
    const int arow_b = wm * 64 + (lane & 15);
    const int ahalf  = lane >> 4;
    const int brow_l = (lane & 7) + ((lane >> 4) << 3);   // pair-local B row 0..15
    const int bhalf  = (lane >> 3) & 1;

    // ---- mainloop: pair-local sync only; pairs free-run ----
    for (int ks = 0; ks < CHUNKS; ++ks) {
        asm volatile("cp.async.wait_group 1;" ::: "memory");
        asm volatile("bar.sync %0, 64;" :: "r"(1 + pair) : "memory");

        int nk = ks + 2;
        if (nk < CHUNKS) load_B(nk, nk % STAGES);
        else asm volatile("cp.async.commit_group;" ::: "memory");

        const int tap = ks >> 1, hc = ks & 1;
        const int aoff = (tap / 3) * 34 + (tap % 3);    // row shift into A buffer (>=0)
        const uint32_t stB = sb + A_BYTES + (pair * STAGES + (ks % STAGES)) * PSTAGE_SZ;
        const char* pB = smem + A_BYTES + (pair * STAGES + (ks % STAGES)) * PSTAGE_SZ;

#pragma unroll
        for (int k32 = 0; k32 < 4; ++k32) {
            // ---- IMMA slice: 1 B-ldsm + 4 A-ldsm + 8 IMMA ----
            uint32_t bb[4];
            {
                uint32_t addr = stB + brow_l * 128 + (((k32 * 2 + bhalf) ^ (brow_l & 7)) << 4);
                ldsm_x4(bb, addr);
            }
#pragma unroll
            for (int mt = 0; mt < 4; ++mt) {
                uint32_t a[4];
                int lr = arow_b + mt * 16 + aoff;
                uint32_t addr = sb + lr * 256 + hc * 128
                              + (((k32 * 2 + ahalf) ^ (lr & 7)) << 4);
                ldsm_x4(a, addr);
                imma(acc[mt][0], a, bb[0], bb[1]);
                imma(acc[mt][1], a, bb[2], bb[3]);
            }
            // ---- dp4a slice: t = 2*k32, 2*k32+1; pair-local rows 16+ws*8.. ----
#pragma unroll
            for (int tt = 0; tt < 2; ++tt) {
                int t = k32 * 2 + tt;
                int4 xv[4];
#pragma unroll
                for (int i = 0; i < 4; ++i) {
                    int lr = lane + 32 * i + aoff;
                    xv[i] = *reinterpret_cast<const int4*>(
                        smem + lr * 256 + hc * 128 + ((t ^ (lr & 7)) << 4));
                }
#pragma unroll
                for (int ob = 0; ob < 2; ++ob) {
                    int4 wv[4];
#pragma unroll
                    for (int oo = 0; oo < 4; ++oo) {
                        int rB = 16 + ws * 8 + ob * 4 + oo;    // pair-local row
                        wv[oo] = *reinterpret_cast<const int4*>(pB + rB * 128 + ((t ^ (rB & 7)) << 4));
                    }
#pragma unroll
                    for (int oo = 0; oo < 4; ++oo) {
                        int o = ob * 4 + oo;
#pragma unroll
                        for (int i = 0; i < 4; ++i) {
                            accd[i][o] = __dp4a(xv[i].x, wv[oo].x, accd[i][o]);
                            accd[i][o] = __dp4a(xv[i].y, wv[oo].y, accd[i][o]);
                            accd[i][o] = __dp4a(xv[i].z, wv[oo].z, accd[i][o]);
                            accd[i][o] = __dp4a(xv[i].w, wv[oo].w, accd[i][o]);
                        }
                    }
                }
            }
        }
    }

    // ---- epilogue: all results -> smem -> quantize -> coalesced store ----
    asm volatile("cp.async.wait_group 0;" ::: "memory");
    __syncthreads();
    int* sEp = reinterpret_cast<int*>(smem);      // [128][EPS]
    {
        const int gq = lane >> 2, tg = lane & 3;
#pragma unroll
        for (int mt = 0; mt < 4; ++mt) {
            int m = wm * 64 + mt * 16 + gq;
#pragma unroll
            for (int nt = 0; nt < 2; ++nt) {
                int n = wn * 16 + nt * 8 + tg * 2;
                sEp[m * EPS + n]           = acc[mt][nt][0];
                sEp[m * EPS + n + 1]       = acc[mt][nt][1];
                sEp[(m + 8) * EPS + n]     = acc[mt][nt][2];
                sEp[(m + 8) * EPS + n + 1] = acc[mt][nt][3];
            }
        }
#pragma unroll
        for (int i = 0; i < 4; ++i) {
            int m = lane + 32 * i;
#pragma unroll
            for (int o = 0; o < 8; ++o)
                sEp[m * EPS + 64 + wid * 8 + o] = accd[i][o];
        }
    }
    __syncthreads();

#pragma unroll 4
    for (int i = 0; i < 64; ++i) {
        int idx = i * 256 + tid;
        int m  = idx & 127;
        int oc = idx >> 7;
        int p = m0 + m;
        int b = p / 1156;
        int rem = p - b * 1156;
        int hp = rem / 34;
        int wp = rem - hp * 34;
        if (b < 32 && hp >= 1 && hp <= 32 && wp >= 1 && wp <= 32) {
            int o = n0 + oc;
            float y = __fmul_rn(__fmul_rn((float)sEp[m * EPS + oc], 0.0078125f), g_scale[o]);
            y = __fadd_rn(y, g_bias[o]);
            float r = rintf(__fmul_rn(y, 2.0f));
            r = fminf(fmaxf(r, -2.0f), 1.0f);
            out[(((size_t)b * 256 + o) * 32 + hp - 1) * 32 + wp - 1] = __fmul_rn(r, 0.5f);
        }
    }
}

extern "C" void kernel_launch(void* const* d_in, const int* in_sizes, int n_in,
                              void* d_out, int out_size) {
    const float* x     = (const float*)d_in[0];
    const float* wt    = (const float*)d_in[1];
    const float* gamma = (const float*)d_in[2];
    const float* beta  = (const float*)d_in[3];
    const float* mean  = (const float*)d_in[4];
    const float* var   = (const float*)d_in[5];
    float* out = (float*)d_out;

    void* xq_ptr = nullptr;
    cudaGetSymbolAddress(&xq_ptr, g_xq);
    cudaMemsetAsync(xq_ptr, 0, sizeof(g_xq), 0);

    quantX_kernel<<<dim3(32, 32), 256>>>(x);
    quantW_kernel<<<2304, 256>>>(wt);
    bn_kernel<<<1, 256>>>(gamma, beta, mean, var);

    cudaFuncSetAttribute(conv_hybrid_kernel, cudaFuncAttributeMaxDynamicSharedMemorySize, SMEM_BYTES);
    conv_hybrid_kernel<<<dim3(289, 2), 256, SMEM_BYTES>>>(out);
}

// round 15
// speedup vs baseline: 1.1557x; 1.0446x over previous
#include <cuda_runtime.h>
#include <math.h>
#include <stdint.h>

// ---------------- problem constants ----------------
#define MTOT 36992            // 32 * 34 * 34 flattened padded rows
#define KTOT 2304             // 9 taps * 256 channels
#define CHUNKS 18             // 9 taps * 2 half-channel groups (128B of K each)
#define AROWS 134             // rows m0-35 .. m0+98 (M64 tile + 3x3 halo reach)

// ---------------- device scratch (no allocs allowed) ----------------
__device__ __align__(256) int8_t g_xq[(size_t)32 * 34 * 34 * 256]; // [b][hp][wp][c], halo zero
__device__ __align__(256) int8_t g_wq[(size_t)256 * KTOT];         // [o][tap*256 + c] ternary
__device__ float g_scale[256];
__device__ float g_bias[256];

// ---------------------------------------------------------------------------
// Pre-pass A: quantize x to int8 (scale 2^-7), NCHW -> padded NHWC
// ---------------------------------------------------------------------------
__global__ void quantX_kernel(const float* __restrict__ x) {
    __shared__ int8_t s[256][33];
    int b = blockIdx.x, h = blockIdx.y;
    int w  = threadIdx.x & 31;
    int cg = threadIdx.x >> 5;
#pragma unroll
    for (int c0 = 0; c0 < 256; c0 += 8) {
        int c = c0 + cg;
        float v = x[(((size_t)(b * 256 + c) * 32 + h) * 32) + w];
        float r = rintf(v * 128.0f);
        r = fminf(fmaxf(r, -128.0f), 127.0f);
        s[c][w] = (int8_t)(int)r;
    }
    __syncthreads();
    size_t base = (((size_t)(b * 34 + h + 1)) * 34 + 1) * 256;
#pragma unroll
    for (int it = 0; it < 8; ++it) {
        int idx = it * 256 + threadIdx.x;
        int w2 = idx >> 6, cw = idx & 63;
        char4 v;
        v.x = s[cw * 4 + 0][w2];
        v.y = s[cw * 4 + 1][w2];
        v.z = s[cw * 4 + 2][w2];
        v.w = s[cw * 4 + 3][w2];
        *reinterpret_cast<char4*>(&g_xq[base + (size_t)w2 * 256 + cw * 4]) = v;
    }
}

// ---------------------------------------------------------------------------
// Pre-pass B: ternary weights, OIHW -> [o][tap*256 + c]
// ---------------------------------------------------------------------------
__global__ void quantW_kernel(const float* __restrict__ wt) {
    int idx = blockIdx.x * 256 + threadIdx.x;   // 589824 total
    int o = idx / KTOT;
    int r = idx - o * KTOT;
    int t = r >> 8;
    int c = r & 255;
    float v = wt[((size_t)(o * 256 + c)) * 9 + t];
    float q = rintf(v);
    q = fminf(fmaxf(q, -1.0f), 1.0f);
    g_wq[(size_t)o * KTOT + r] = (int8_t)(int)q;
}

// ---------------------------------------------------------------------------
// Pre-pass C: BN fold
// ---------------------------------------------------------------------------
__global__ void bn_kernel(const float* __restrict__ g, const float* __restrict__ be,
                          const float* __restrict__ m, const float* __restrict__ v) {
    int o = threadIdx.x;
    double invd = (double)g[o] / sqrt((double)v[o] + 1e-4);
    float invf = (float)invd;
    g_scale[o] = invf;
    g_bias[o]  = __fadd_rn(be[o], -__fmul_rn(m[o], invf));
}

// ---------------- helpers ----------------
__device__ __forceinline__ uint32_t smem_u32(const void* p) {
    uint32_t a;
    asm("{ .reg .u64 t; cvta.to.shared.u64 t, %1; cvt.u32.u64 %0, t; }" : "=r"(a) : "l"(p));
    return a;
}
__device__ __forceinline__ void cp_async_16(uint32_t dst, const void* src, unsigned srcsz) {
    asm volatile("cp.async.cg.shared.global [%0], [%1], 16, %2;"
                 :: "r"(dst), "l"(src), "r"(srcsz));
}
__device__ __forceinline__ void ldsm_x4(uint32_t* r, uint32_t addr) {
    asm volatile("ldmatrix.sync.aligned.m8n8.x4.shared.b16 {%0,%1,%2,%3}, [%4];"
                 : "=r"(r[0]), "=r"(r[1]), "=r"(r[2]), "=r"(r[3]) : "r"(addr));
}
__device__ __forceinline__ void imma(int* c, const uint32_t* a, uint32_t b0, uint32_t b1) {
    asm volatile(
        "mma.sync.aligned.m16n8k32.row.col.s32.s8.s8.s32 "
        "{%0,%1,%2,%3}, {%4,%5,%6,%7}, {%8,%9}, {%0,%1,%2,%3};"
        : "+r"(c[0]), "+r"(c[1]), "+r"(c[2]), "+r"(c[3])
        : "r"(a[0]), "r"(a[1]), "r"(a[2]), "r"(a[3]), "r"(b0), "r"(b1));
}

// smem: A persistent [134 rows x 256B] = 34304,
// then per-pair B rings: pair p, slot s(0/1) at A_BYTES + (p*2+s)*4096
// (pair slice = 32 rows x 128B: 16 IMMA rows [16p,16p+16) local 0..15,
//  16 dp4a rows [64+16p,+16) local 16..31)
#define A_BYTES   34304
#define PSTAGE_SZ 4096
#define SMEM_BYTES (A_BYTES + 4 * 2 * PSTAGE_SZ)   // 67072 -> 3 CTAs/SM
#define EPS 129

__global__ void __launch_bounds__(256, 3) conv_hybrid_kernel(float* __restrict__ out) {
    extern __shared__ __align__(256) char smem[];
    const uint32_t sb = smem_u32(smem);
    const int tid  = threadIdx.x;
    const int wid  = tid >> 5;
    const int lane = tid & 31;
    const int pair = wid >> 1;          // 0..3 (== wn)
    const int ws   = wid & 1;           // warp-in-pair (== wm)
    const int ptid = tid & 63;
    const int m0 = blockIdx.x * 64;
    const int n0 = blockIdx.y * 128;

    // Every warp: IMMA sub-tile 32M x 16N over local N[0:64], dp4a 2m x 8o over N[64:128]
    int acc[2][2][4];
    int accd[2][8];
#pragma unroll
    for (int mt = 0; mt < 2; ++mt)
#pragma unroll
        for (int nt = 0; nt < 2; ++nt)
#pragma unroll
            for (int r = 0; r < 4; ++r) acc[mt][nt][r] = 0;
#pragma unroll
    for (int i = 0; i < 2; ++i)
#pragma unroll
        for (int o = 0; o < 8; ++o) accd[i][o] = 0;

    // ---- per-pair B loader: 64 threads load the pair's 32 rows into slot ks&1 ----
    auto load_B = [&](int ks) {
        const int tap = ks >> 1, hc = ks & 1;
        const uint32_t stB = sb + A_BYTES + (pair * 2 + (ks & 1)) * PSTAGE_SZ;
#pragma unroll
        for (int it = 0; it < 4; ++it) {
            int idx = it * 64 + ptid;          // 0..255
            int r = idx >> 3, c16 = idx & 7;   // r 0..31 local
            int grow = (r < 16) ? (16 * pair + r) : (64 + 16 * pair + (r - 16));
            uint32_t soff = (uint32_t)(r * 128 + ((c16 ^ (r & 7)) << 4));
            const int8_t* srcB = g_wq + (size_t)(n0 + grow) * KTOT + tap * 256 + hc * 128 + c16 * 16;
            cp_async_16(stB + soff, srcB, 16u);
        }
        asm volatile("cp.async.commit_group;" ::: "memory");
    };

    // ---- prologue: persistent A (134 rows, zfill halo) + B0; publish ----
    {
        const long rowbase = (long)m0 - 35;
        for (int idx = tid; idx < AROWS * 16; idx += 256) {
            int r = idx >> 4, c16 = idx & 15;
            uint32_t dst = sb + (uint32_t)(r * 256 + ((c16 ^ (r & 7)) << 4));
            long g = rowbase + r;
            const int8_t* src = g_xq + g * 256 + c16 * 16;
            unsigned sz = (g >= 0 && g < MTOT) ? 16u : 0u;
            cp_async_16(dst, src, sz);
        }
        asm volatile("cp.async.commit_group;" ::: "memory");
        load_B(0);
        asm volatile("cp.async.wait_group 0;" ::: "memory");
        __syncthreads();
    }

    // IMMA fragment row bases: warps as 2M x 4N (warp tile 32M x 16N)
    const int arow_b = ws * 32 + (lane & 15);
    const int ahalf  = lane >> 4;
    const int brow_l = (lane & 7) + ((lane >> 4) << 3);   // pair-local B row 0..15
    const int bhalf  = (lane >> 3) & 1;

    // ---- mainloop: pair-local sync only ----
    for (int ks = 0; ks < CHUNKS; ++ks) {
        if (ks + 1 < CHUNKS) load_B(ks + 1);

        const int tap = ks >> 1, hc = ks & 1;
        const int aoff = (tap / 3) * 34 + (tap % 3);    // row shift into A buffer (>=0)
        const uint32_t stB = sb + A_BYTES + (pair * 2 + (ks & 1)) * PSTAGE_SZ;
        const char* pB = smem + A_BYTES + (pair * 2 + (ks & 1)) * PSTAGE_SZ;

#pragma unroll
        for (int k32 = 0; k32 < 4; ++k32) {
            // ---- IMMA slice: 1 B-ldsm + 2 A-ldsm + 4 IMMA ----
            uint32_t bb[4];
            {
                uint32_t addr = stB + brow_l * 128 + (((k32 * 2 + bhalf) ^ (brow_l & 7)) << 4);
                ldsm_x4(bb, addr);
            }
#pragma unroll
            for (int mt = 0; mt < 2; ++mt) {
                uint32_t a[4];
                int lr = arow_b + mt * 16 + aoff;
                uint32_t addr = sb + lr * 256 + hc * 128
                              + (((k32 * 2 + ahalf) ^ (lr & 7)) << 4);
                ldsm_x4(a, addr);
                imma(acc[mt][0], a, bb[0], bb[1]);
                imma(acc[mt][1], a, bb[2], bb[3]);
            }
            // ---- dp4a slice: t = 2*k32, 2*k32+1 ----
#pragma unroll
            for (int tt = 0; tt < 2; ++tt) {
                int t = k32 * 2 + tt;
                int4 xv[2];
#pragma unroll
                for (int i = 0; i < 2; ++i) {
                    int lr = lane + 32 * i + aoff;
                    xv[i] = *reinterpret_cast<const int4*>(
                        smem + lr * 256 + hc * 128 + ((t ^ (lr & 7)) << 4));
                }
#pragma unroll
                for (int ob = 0; ob < 2; ++ob) {
                    int4 wv[4];
#pragma unroll
                    for (int oo = 0; oo < 4; ++oo) {
                        int rB = 16 + ws * 8 + ob * 4 + oo;    // pair-local row
                        wv[oo] = *reinterpret_cast<const int4*>(pB + rB * 128 + ((t ^ (rB & 7)) << 4));
                    }
#pragma unroll
                    for (int oo = 0; oo < 4; ++oo) {
                        int o = ob * 4 + oo;
#pragma unroll
                        for (int i = 0; i < 2; ++i) {
                            accd[i][o] = __dp4a(xv[i].x, wv[oo].x, accd[i][o]);
                            accd[i][o] = __dp4a(xv[i].y, wv[oo].y, accd[i][o]);
                            accd[i][o] = __dp4a(xv[i].z, wv[oo].z, accd[i][o]);
                            accd[i][o] = __dp4a(xv[i].w, wv[oo].w, accd[i][o]);
                        }
                    }
                }
            }
        }

        if (ks + 1 < CHUNKS) {
            asm volatile("cp.async.wait_group 0;" ::: "memory");
            asm volatile("bar.sync %0, 64;" :: "r"(1 + pair) : "memory");
        }
    }

    // ---- epilogue: results -> smem -> quantize -> coalesced store ----
    __syncthreads();
    int* sEp = reinterpret_cast<int*>(smem);      // [64][EPS]
    {
        const int gq = lane >> 2, tg = lane & 3;
#pragma unroll
        for (int mt = 0; mt < 2; ++mt) {
            int m = ws * 32 + mt * 16 + gq;
#pragma unroll
            for (int nt = 0; nt < 2; ++nt) {
                int n = pair * 16 + nt * 8 + tg * 2;
                sEp[m * EPS + n]           = acc[mt][nt][0];
                sEp[m * EPS + n + 1]       = acc[mt][nt][1];
                sEp[(m + 8) * EPS + n]     = acc[mt][nt][2];
                sEp[(m + 8) * EPS + n + 1] = acc[mt][nt][3];
            }
        }
#pragma unroll
        for (int i = 0; i < 2; ++i) {
            int m = lane + 32 * i;
#pragma unroll
            for (int o = 0; o < 8; ++o)
                sEp[m * EPS + 64 + pair * 16 + ws * 8 + o] = accd[i][o];
        }
    }
    __syncthreads();

#pragma unroll 4
    for (int i = 0; i < 32; ++i) {
        int idx = i * 256 + tid;      // 8192 outputs
        int m  = idx & 63;
        int oc = idx >> 6;            // 0..127
        int p = m0 + m;
        int b = p / 1156;
        int rem = p - b * 1156;
        int hp = rem / 34;
        int wp = rem - hp * 34;
        if (b < 32 && hp >= 1 && hp <= 32 && wp >= 1 && wp <= 32) {
            int o = n0 + oc;
            float y = __fmul_rn(__fmul_rn((float)sEp[m * EPS + oc], 0.0078125f), g_scale[o]);
            y = __fadd_rn(y, g_bias[o]);
            float r = rintf(__fmul_rn(y, 2.0f));
            r = fminf(fmaxf(r, -2.0f), 1.0f);
            out[(((size_t)b * 256 + o) * 32 + hp - 1) * 32 + wp - 1] = __fmul_rn(r, 0.5f);
        }
    }
}

extern "C" void kernel_launch(void* const* d_in, const int* in_sizes, int n_in,
                              void* d_out, int out_size) {
    const float* x     = (const float*)d_in[0];
    const float* wt    = (const float*)d_in[1];
    const float* gamma = (const float*)d_in[2];
    const float* beta  = (const float*)d_in[3];
    const float* mean  = (const float*)d_in[4];
    const float* var   = (const float*)d_in[5];
    float* out = (float*)d_out;

    void* xq_ptr = nullptr;
    cudaGetSymbolAddress(&xq_ptr, g_xq);
    cudaMemsetAsync(xq_ptr, 0, sizeof(g_xq), 0);

    quantX_kernel<<<dim3(32, 32), 256>>>(x);
    quantW_kernel<<<2304, 256>>>(wt);
    bn_kernel<<<1, 256>>>(gamma, beta, mean, var);

    cudaFuncSetAttribute(conv_hybrid_kernel, cudaFuncAttributeMaxDynamicSharedMemorySize, SMEM_BYTES);
    conv_hybrid_kernel<<<dim3(578, 2), 256, SMEM_BYTES>>>(out);
}